// round 6
// baseline (speedup 1.0000x reference)
#include <cuda_runtime.h>
#include <cuda_bf16.h>
#include <math.h>
#include <stdint.h>

#define BB 4
#define SS 4096
#define DD 256
#define UU 64
#define NTILES (SS / 64)
#define NROWS (BB * SS)        // 16384

// Scratch (no cudaMalloc allowed)
__device__ float          g_q [NROWS * UU];        // fp32  [b][s][u]
__device__ __nv_bfloat16  g_kh[NROWS * UU];        // K hi, natural [b][s][u]
__device__ __nv_bfloat16  g_kl[NROWS * UU];
__device__ __nv_bfloat16  g_vh[NROWS * UU];        // V hi, natural [b][s][u]
__device__ __nv_bfloat16  g_vl[NROWS * UU];
__device__ __nv_bfloat16  g_wh[DD * 192];          // W combined [d][mat*64+u] hi
__device__ __nv_bfloat16  g_wl[DD * 192];          // lo

// ---------------------------------------------------------------------------
// helpers
// ---------------------------------------------------------------------------
__device__ __forceinline__ void ldsm2t(uint32_t& r0, uint32_t& r1, uint32_t a)
{   // transposed: tile rows = k-dim
    asm volatile("ldmatrix.sync.aligned.m8n8.x2.trans.shared.b16 {%0,%1},[%2];"
                 : "=r"(r0), "=r"(r1) : "r"(a));
}
__device__ __forceinline__ void ldsm2n(uint32_t& r0, uint32_t& r1, uint32_t a)
{   // non-transposed: tile rows = n-dim, cols = k contiguous
    asm volatile("ldmatrix.sync.aligned.m8n8.x2.shared.b16 {%0,%1},[%2];"
                 : "=r"(r0), "=r"(r1) : "r"(a));
}
__device__ __forceinline__ void mma16(float d[4],
                                      uint32_t a0, uint32_t a1, uint32_t a2, uint32_t a3,
                                      uint32_t b0, uint32_t b1)
{
    asm volatile(
        "mma.sync.aligned.m16n8k16.row.col.f32.bf16.bf16.f32 "
        "{%0,%1,%2,%3},{%4,%5,%6,%7},{%8,%9},{%0,%1,%2,%3};\n"
        : "+f"(d[0]), "+f"(d[1]), "+f"(d[2]), "+f"(d[3])
        : "r"(a0), "r"(a1), "r"(a2), "r"(a3), "r"(b0), "r"(b1));
}
__device__ __forceinline__ uint32_t bsplit(float x, float y, uint32_t& lo)
{
    __nv_bfloat162 h2 = __floats2bfloat162_rn(x, y);
    const float rx = x - __bfloat162float(h2.x);
    const float ry = y - __bfloat162float(h2.y);
    __nv_bfloat162 l2 = __floats2bfloat162_rn(rx, ry);
    lo = *(uint32_t*)&l2;
    return *(uint32_t*)&h2;
}
__device__ __forceinline__ void cpa16(void* dst, const void* src)
{
    uint32_t d = (uint32_t)__cvta_generic_to_shared(dst);
    asm volatile("cp.async.cg.shared.global [%0],[%1],16;\n" :: "r"(d), "l"(src));
}
__device__ __forceinline__ void cpa_commit()
{
    asm volatile("cp.async.commit_group;\n" ::: "memory");
}
__device__ __forceinline__ void cpa_wait0()
{
    asm volatile("cp.async.wait_group 0;\n" ::: "memory");
}

// ---------------------------------------------------------------------------
// W convert: fp32 Wq|Wk|Wv -> bf16 hi/lo planes [d][192], col = mat*64+u
// ---------------------------------------------------------------------------
__global__ __launch_bounds__(256) void wconv_kernel(
    const float* __restrict__ Wq, const float* __restrict__ Wk,
    const float* __restrict__ Wv)
{
    const int idx = blockIdx.x * 256 + threadIdx.x;   // 0 .. 256*192-1
    const int d = idx / 192;
    const int n = idx % 192;
    const int mat = n >> 6;
    const int u   = n & 63;
    const float* W = (mat == 0) ? Wq : (mat == 1) ? Wk : Wv;
    const float v = W[d * UU + u];
    const __nv_bfloat16 h = __float2bfloat16(v);
    g_wh[idx] = h;
    g_wl[idx] = __float2bfloat16(v - __bfloat162float(h));
}

// ---------------------------------------------------------------------------
// Projection GEMM on tensor cores: [64 rows/block] x W[256,192], 3-term bf16.
// 8 warps: wr = w>>1 row group (16 rows), wc = w&1 col half (96 cols, 12 j).
// W chunk (64 k-rows) in swizzled smem; A-fragments split from fp32 x.
// ---------------------------------------------------------------------------
__global__ __launch_bounds__(256) void proj_kernel(
    const float* __restrict__ x,
    const float* __restrict__ bq, const float* __restrict__ bk,
    const float* __restrict__ bv)
{
    __shared__ __align__(16) __nv_bfloat16 WH[64 * 192];   // 24 KB
    __shared__ __align__(16) __nv_bfloat16 WL[64 * 192];   // 24 KB

    const int R0  = blockIdx.x * 64;
    const int tid = threadIdx.x;
    const int w = tid >> 5, lane = tid & 31;
    const int wr = w >> 1, wc = w & 1;
    const int g = lane >> 2, q = lane & 3, lr = lane & 15;
    const int r0 = 16 * wr + g;

    float Of[12][4];
#pragma unroll
    for (int j = 0; j < 12; j++)
#pragma unroll
        for (int i = 0; i < 4; i++) Of[j][i] = 0.f;

    for (int kc = 0; kc < 4; kc++) {
        __syncthreads();
        // load W chunk [64][192] hi/lo, swizzled 8-chunk XOR
#pragma unroll
        for (int i0 = 0; i0 < 6; i0++) {
            const int i = tid + i0 * 256;
            const int d = i / 24;
            const int c = i % 24;
            const int sw = d * 192 + ((c ^ (d & 7)) * 8);
            *(uint4*)&WH[sw] = *(const uint4*)(g_wh + (size_t)(kc * 64 + d) * 192 + c * 8);
            *(uint4*)&WL[sw] = *(const uint4*)(g_wl + (size_t)(kc * 64 + d) * 192 + c * 8);
        }
        __syncthreads();

#pragma unroll
        for (int t = 0; t < 4; t++) {
            const int k0 = kc * 64 + 16 * t;
            float2 x0 = *(const float2*)(x + (size_t)(R0 + r0)     * DD + k0 + 2 * q);
            float2 x1 = *(const float2*)(x + (size_t)(R0 + r0 + 8) * DD + k0 + 2 * q);
            float2 x2 = *(const float2*)(x + (size_t)(R0 + r0)     * DD + k0 + 8 + 2 * q);
            float2 x3 = *(const float2*)(x + (size_t)(R0 + r0 + 8) * DD + k0 + 8 + 2 * q);
            uint32_t al0, al1, al2, al3;
            const uint32_t ah0 = bsplit(x0.x, x0.y, al0);
            const uint32_t ah1 = bsplit(x1.x, x1.y, al1);
            const uint32_t ah2 = bsplit(x2.x, x2.y, al2);
            const uint32_t ah3 = bsplit(x3.x, x3.y, al3);

#pragma unroll
            for (int j = 0; j < 12; j++) {
                const int cc = 12 * wc + j;
                const int r  = 16 * t + lr;
                const int sw = r * 192 + ((cc ^ (r & 7)) * 8);
                uint32_t wh0, wh1, wl0, wl1;
                ldsm2t(wh0, wh1, (uint32_t)__cvta_generic_to_shared(&WH[sw]));
                ldsm2t(wl0, wl1, (uint32_t)__cvta_generic_to_shared(&WL[sw]));
                mma16(Of[j], ah0, ah1, ah2, ah3, wh0, wh1);
                mma16(Of[j], ah0, ah1, ah2, ah3, wl0, wl1);
                mma16(Of[j], al0, al1, al2, al3, wh0, wh1);
            }
        }
    }

    // epilogue: bias, route by matrix, split K/V to bf16 hi/lo
#pragma unroll
    for (int j = 0; j < 12; j++) {
        const int n   = 96 * wc + 8 * j + 2 * q;
        const int mat = n >> 6;
        const int u   = n & 63;
        const float* bp = (mat == 0) ? bq : (mat == 1) ? bk : bv;
        const float b0v = bp[u], b1v = bp[u + 1];
        const float v00 = Of[j][0] + b0v, v01 = Of[j][1] + b1v;   // row r0
        const float v10 = Of[j][2] + b0v, v11 = Of[j][3] + b1v;   // row r0+8
        const size_t o0 = (size_t)(R0 + r0)     * UU + u;
        const size_t o1 = (size_t)(R0 + r0 + 8) * UU + u;
        if (mat == 0) {
            *(float2*)(g_q + o0) = make_float2(v00, v01);
            *(float2*)(g_q + o1) = make_float2(v10, v11);
        } else if (mat == 1) {
            uint32_t lo0, lo1;
            const uint32_t h0 = bsplit(v00, v01, lo0);
            const uint32_t h1 = bsplit(v10, v11, lo1);
            *(uint32_t*)(g_kh + o0) = h0;  *(uint32_t*)(g_kl + o0) = lo0;
            *(uint32_t*)(g_kh + o1) = h1;  *(uint32_t*)(g_kl + o1) = lo1;
        } else {
            uint32_t lo0, lo1;
            const uint32_t h0 = bsplit(v00, v01, lo0);
            const uint32_t h1 = bsplit(v10, v11, lo1);
            *(uint32_t*)(g_vh + o0) = h0;  *(uint32_t*)(g_vl + o0) = lo0;
            *(uint32_t*)(g_vh + o1) = h1;  *(uint32_t*)(g_vl + o1) = lo1;
        }
    }
}

// ---------------------------------------------------------------------------
// Flash attention: 256 threads = 8 warps. Warp (wr, half): 16 rows x 32 keys.
// cp.async double-buffered K/V tiles (bf16 hi/lo, swizzled). S B-fragments
// via non-trans ldmatrix from natural K tile; PV via trans ldmatrix from V.
// Per-warp online softmax over its key half; final split-K merge via smem.
// ---------------------------------------------------------------------------
__global__ __launch_bounds__(256) void attn_kernel(float* __restrict__ out)
{
    extern __shared__ __align__(16) __nv_bfloat16 SB[];   // 8 * 4096 bf16 = 64 KB
    // tile base: SB + (buf*4 + arr)*4096 ; arr: 0=KH 1=KL 2=VH 3=VL

    const int b   = blockIdx.x >> 6;
    const int mt  = blockIdx.x & 63;
    const int tid = threadIdx.x;
    const int w = tid >> 5, lane = tid & 31;
    const int half = w >> 2, wr = w & 3;
    const int g = lane >> 2, q = lane & 3, lr = lane & 15;
    const int r0 = 16 * wr + g;

    const __nv_bfloat16* khg = g_kh + (size_t)b * SS * UU;
    const __nv_bfloat16* klg = g_kl + (size_t)b * SS * UU;
    const __nv_bfloat16* vhg = g_vh + (size_t)b * SS * UU;
    const __nv_bfloat16* vlg = g_vl + (size_t)b * SS * UU;

    // ---- Q fragments: fold 1/8, split hi/lo ----
    uint32_t qh[4][4], ql[4][4];
    {
        const float* qg = g_q + ((size_t)b * SS + mt * 64) * UU;
#pragma unroll
        for (int t = 0; t < 4; t++) {
            float2 x0 = *(const float2*)(qg + (size_t)(r0)     * UU + 16 * t + 2 * q);
            float2 x1 = *(const float2*)(qg + (size_t)(r0 + 8) * UU + 16 * t + 2 * q);
            float2 x2 = *(const float2*)(qg + (size_t)(r0)     * UU + 16 * t + 8 + 2 * q);
            float2 x3 = *(const float2*)(qg + (size_t)(r0 + 8) * UU + 16 * t + 8 + 2 * q);
            qh[t][0] = bsplit(x0.x * 0.125f, x0.y * 0.125f, ql[t][0]);
            qh[t][1] = bsplit(x1.x * 0.125f, x1.y * 0.125f, ql[t][1]);
            qh[t][2] = bsplit(x2.x * 0.125f, x2.y * 0.125f, ql[t][2]);
            qh[t][3] = bsplit(x3.x * 0.125f, x3.y * 0.125f, ql[t][3]);
        }
    }

    float Of[8][4];
#pragma unroll
    for (int j = 0; j < 8; j++)
#pragma unroll
        for (int i = 0; i < 4; i++) Of[j][i] = 0.f;
    float m0 = -1e30f, m1 = -1e30f, l0 = 0.f, l1 = 0.f;

    auto load_tile = [&](int nt, int buf) {
        const size_t base = (size_t)(nt * 64) * UU;
        __nv_bfloat16* B0 = SB + (buf * 4 + 0) * 4096;
        __nv_bfloat16* B1 = SB + (buf * 4 + 1) * 4096;
        __nv_bfloat16* B2 = SB + (buf * 4 + 2) * 4096;
        __nv_bfloat16* B3 = SB + (buf * 4 + 3) * 4096;
#pragma unroll
        for (int i0 = 0; i0 < 2; i0++) {
            const int i   = tid + i0 * 256;
            const int row = i >> 3;
            const int c   = i & 7;
            const int sw  = row * 64 + ((c ^ (row & 7)) * 8);
            const size_t src = base + (size_t)row * UU + c * 8;
            cpa16(B0 + sw, khg + src);
            cpa16(B1 + sw, klg + src);
            cpa16(B2 + sw, vhg + src);
            cpa16(B3 + sw, vlg + src);
        }
        cpa_commit();
    };

    load_tile(0, 0);

    for (int nt = 0; nt < NTILES; nt++) {
        const int buf = nt & 1;
        cpa_wait0();
        __syncthreads();
        if (nt + 1 < NTILES) load_tile(nt + 1, buf ^ 1);

        const __nv_bfloat16* KHp = SB + (buf * 4 + 0) * 4096;
        const __nv_bfloat16* KLp = SB + (buf * 4 + 1) * 4096;
        const __nv_bfloat16* VHp = SB + (buf * 4 + 2) * 4096;
        const __nv_bfloat16* VLp = SB + (buf * 4 + 3) * 4096;

        // ---- S = Q K^T over this warp's 32-key half ----
        float Sf[4][4];
#pragma unroll
        for (int jj = 0; jj < 4; jj++) {
            Sf[jj][0] = Sf[jj][1] = Sf[jj][2] = Sf[jj][3] = 0.f;
            const int j = 4 * half + jj;
            const int rowb = 8 * j + (lr & 7);
#pragma unroll
            for (int t = 0; t < 4; t++) {
                const int c  = 2 * t + (lr >> 3);
                const int sw = rowb * 64 + ((c ^ (rowb & 7)) * 8);
                uint32_t bh0, bh1, bl0, bl1;
                ldsm2n(bh0, bh1, (uint32_t)__cvta_generic_to_shared(&KHp[sw]));
                ldsm2n(bl0, bl1, (uint32_t)__cvta_generic_to_shared(&KLp[sw]));
                mma16(Sf[jj], qh[t][0], qh[t][1], qh[t][2], qh[t][3], bh0, bh1);
                mma16(Sf[jj], qh[t][0], qh[t][1], qh[t][2], qh[t][3], bl0, bl1);
                mma16(Sf[jj], ql[t][0], ql[t][1], ql[t][2], ql[t][3], bh0, bh1);
            }
        }

        // ---- online softmax over the 32-col half ----
        float rm0 = -1e30f, rm1 = -1e30f;
#pragma unroll
        for (int jj = 0; jj < 4; jj++) {
            rm0 = fmaxf(rm0, fmaxf(Sf[jj][0], Sf[jj][1]));
            rm1 = fmaxf(rm1, fmaxf(Sf[jj][2], Sf[jj][3]));
        }
        rm0 = fmaxf(rm0, __shfl_xor_sync(0xffffffffu, rm0, 1));
        rm0 = fmaxf(rm0, __shfl_xor_sync(0xffffffffu, rm0, 2));
        rm1 = fmaxf(rm1, __shfl_xor_sync(0xffffffffu, rm1, 1));
        rm1 = fmaxf(rm1, __shfl_xor_sync(0xffffffffu, rm1, 2));

        const float mn0 = fmaxf(m0, rm0);
        const float mn1 = fmaxf(m1, rm1);
        const float c0  = __expf(m0 - mn0);
        const float c1  = __expf(m1 - mn1);
        m0 = mn0; m1 = mn1;

        float rs0 = 0.f, rs1 = 0.f;
#pragma unroll
        for (int jj = 0; jj < 4; jj++) {
            Sf[jj][0] = __expf(Sf[jj][0] - mn0); rs0 += Sf[jj][0];
            Sf[jj][1] = __expf(Sf[jj][1] - mn0); rs0 += Sf[jj][1];
            Sf[jj][2] = __expf(Sf[jj][2] - mn1); rs1 += Sf[jj][2];
            Sf[jj][3] = __expf(Sf[jj][3] - mn1); rs1 += Sf[jj][3];
        }
        rs0 += __shfl_xor_sync(0xffffffffu, rs0, 1);
        rs0 += __shfl_xor_sync(0xffffffffu, rs0, 2);
        rs1 += __shfl_xor_sync(0xffffffffu, rs1, 1);
        rs1 += __shfl_xor_sync(0xffffffffu, rs1, 2);

        l0 = l0 * c0 + rs0;
        l1 = l1 * c1 + rs1;
#pragma unroll
        for (int j = 0; j < 8; j++) {
            Of[j][0] *= c0; Of[j][1] *= c0;
            Of[j][2] *= c1; Of[j][3] *= c1;
        }

        // ---- P remap to A-fragments (registers only) ----
        uint32_t ph01[4], ph23[4], pl01[4], pl23[4];
#pragma unroll
        for (int jj = 0; jj < 4; jj++) {
            ph01[jj] = bsplit(Sf[jj][0], Sf[jj][1], pl01[jj]);
            ph23[jj] = bsplit(Sf[jj][2], Sf[jj][3], pl23[jj]);
        }

        // ---- O += P V over this warp's 32 keys ----
#pragma unroll
        for (int j = 0; j < 8; j++) {          // u chunks
#pragma unroll
            for (int tt = 0; tt < 2; tt++) {   // key 16-chunks within half
                const int r  = (2 * half + tt) * 16 + lr;
                const int sw = r * 64 + ((j ^ (r & 7)) * 8);
                uint32_t vh0, vh1, vl0, vl1;
                ldsm2t(vh0, vh1, (uint32_t)__cvta_generic_to_shared(&VHp[sw]));
                ldsm2t(vl0, vl1, (uint32_t)__cvta_generic_to_shared(&VLp[sw]));
                mma16(Of[j], ph01[2*tt], ph23[2*tt], ph01[2*tt+1], ph23[2*tt+1], vh0, vh1);
                mma16(Of[j], ph01[2*tt], ph23[2*tt], ph01[2*tt+1], ph23[2*tt+1], vl0, vl1);
                mma16(Of[j], pl01[2*tt], pl23[2*tt], pl01[2*tt+1], pl23[2*tt+1], vh0, vh1);
            }
        }
    }

    // ---- split-K merge: half 0 publishes, half 1 merges + stores ----
    __syncthreads();
    float* MB = (float*)SB;    // 64*64 O + 64 m + 64 l = 16.9 KB, fits
    if (half == 0) {
#pragma unroll
        for (int j = 0; j < 8; j++) {
            *(float2*)&MB[(r0)     * 64 + 8 * j + 2 * q] = make_float2(Of[j][0], Of[j][1]);
            *(float2*)&MB[(r0 + 8) * 64 + 8 * j + 2 * q] = make_float2(Of[j][2], Of[j][3]);
        }
        if (q == 0) {
            MB[4096 + r0]          = m0;  MB[4096 + 64 + r0]     = l0;
            MB[4096 + r0 + 8]      = m1;  MB[4096 + 64 + r0 + 8] = l1;
        }
    }
    __syncthreads();
    if (half == 1) {
        const float ma0 = MB[4096 + r0],     la0 = MB[4096 + 64 + r0];
        const float ma1 = MB[4096 + r0 + 8], la1 = MB[4096 + 64 + r0 + 8];
        const float M0 = fmaxf(ma0, m0), M1 = fmaxf(ma1, m1);
        const float ea0 = __expf(ma0 - M0), eb0 = __expf(m0 - M0);
        const float ea1 = __expf(ma1 - M1), eb1 = __expf(m1 - M1);
        const float iL0 = 1.f / (la0 * ea0 + l0 * eb0);
        const float iL1 = 1.f / (la1 * ea1 + l1 * eb1);
        const float sa0 = ea0 * iL0, sb0 = eb0 * iL0;
        const float sa1 = ea1 * iL1, sb1 = eb1 * iL1;

        float* op = out + ((size_t)b * SS + mt * 64) * UU;
#pragma unroll
        for (int j = 0; j < 8; j++) {
            const float2 pa0 = *(const float2*)&MB[(r0)     * 64 + 8 * j + 2 * q];
            const float2 pa1 = *(const float2*)&MB[(r0 + 8) * 64 + 8 * j + 2 * q];
            *(float2*)(op + (size_t)(r0)     * UU + 8 * j + 2 * q) =
                make_float2(pa0.x * sa0 + Of[j][0] * sb0, pa0.y * sa0 + Of[j][1] * sb0);
            *(float2*)(op + (size_t)(r0 + 8) * UU + 8 * j + 2 * q) =
                make_float2(pa1.x * sa1 + Of[j][2] * sb1, pa1.y * sa1 + Of[j][3] * sb1);
        }
    }
}

// ---------------------------------------------------------------------------
extern "C" void kernel_launch(void* const* d_in, const int* in_sizes, int n_in,
                              void* d_out, int out_size)
{
    const float* x  = (const float*)d_in[0];
    const float* Wq = (const float*)d_in[1];
    const float* bq = (const float*)d_in[2];
    const float* Wk = (const float*)d_in[3];
    const float* bk = (const float*)d_in[4];
    const float* Wv = (const float*)d_in[5];
    const float* bv = (const float*)d_in[6];
    float* out = (float*)d_out;

    wconv_kernel<<<(DD * 192) / 256, 256>>>(Wq, Wk, Wv);
    proj_kernel<<<NROWS / 64, 256>>>(x, bq, bk, bv);

    const int smem_bytes = 8 * 4096 * (int)sizeof(__nv_bfloat16);   // 64 KB
    cudaFuncSetAttribute(attn_kernel, cudaFuncAttributeMaxDynamicSharedMemorySize,
                         smem_bytes);
    attn_kernel<<<BB * (SS / 64), 256, smem_bytes>>>(out);
}

// round 7
// speedup vs baseline: 1.5583x; 1.5583x over previous
#include <cuda_runtime.h>
#include <cuda_bf16.h>
#include <math.h>
#include <stdint.h>

#define BB 4
#define SS 4096
#define DD 256
#define UU 64
#define NTILES (SS / 64)
#define NROWS (BB * SS)        // 16384

// Scratch (no cudaMalloc allowed)
__device__ float          g_q [NROWS * UU];        // fp32  [b][s][u]
__device__ __nv_bfloat16  g_kh[NROWS * UU];        // K hi, natural [b][s][u]
__device__ __nv_bfloat16  g_kl[NROWS * UU];
__device__ __nv_bfloat16  g_vh[NROWS * UU];        // V hi, natural [b][s][u]
__device__ __nv_bfloat16  g_vl[NROWS * UU];
__device__ __nv_bfloat16  g_wh[DD * 192];          // W combined [d][mat*64+u] hi
__device__ __nv_bfloat16  g_wl[DD * 192];          // lo

// ---------------------------------------------------------------------------
// helpers
// ---------------------------------------------------------------------------
__device__ __forceinline__ void ldsm2t(uint32_t& r0, uint32_t& r1, uint32_t a)
{   // transposed: fragment pairs run across tile rows
    asm volatile("ldmatrix.sync.aligned.m8n8.x2.trans.shared.b16 {%0,%1},[%2];"
                 : "=r"(r0), "=r"(r1) : "r"(a));
}
__device__ __forceinline__ void ldsm2n(uint32_t& r0, uint32_t& r1, uint32_t a)
{   // non-transposed: fragment pairs run along tile row (contiguous)
    asm volatile("ldmatrix.sync.aligned.m8n8.x2.shared.b16 {%0,%1},[%2];"
                 : "=r"(r0), "=r"(r1) : "r"(a));
}
__device__ __forceinline__ void mma16(float d[4],
                                      uint32_t a0, uint32_t a1, uint32_t a2, uint32_t a3,
                                      uint32_t b0, uint32_t b1)
{
    asm volatile(
        "mma.sync.aligned.m16n8k16.row.col.f32.bf16.bf16.f32 "
        "{%0,%1,%2,%3},{%4,%5,%6,%7},{%8,%9},{%0,%1,%2,%3};\n"
        : "+f"(d[0]), "+f"(d[1]), "+f"(d[2]), "+f"(d[3])
        : "r"(a0), "r"(a1), "r"(a2), "r"(a3), "r"(b0), "r"(b1));
}
__device__ __forceinline__ uint32_t bsplit(float x, float y, uint32_t& lo)
{
    __nv_bfloat162 h2 = __floats2bfloat162_rn(x, y);
    const float rx = x - __bfloat162float(h2.x);
    const float ry = y - __bfloat162float(h2.y);
    __nv_bfloat162 l2 = __floats2bfloat162_rn(rx, ry);
    lo = *(uint32_t*)&l2;
    return *(uint32_t*)&h2;
}
__device__ __forceinline__ void cpa16(void* dst, const void* src)
{
    uint32_t d = (uint32_t)__cvta_generic_to_shared(dst);
    asm volatile("cp.async.cg.shared.global [%0],[%1],16;\n" :: "r"(d), "l"(src));
}
__device__ __forceinline__ void cpa_commit()
{
    asm volatile("cp.async.commit_group;\n" ::: "memory");
}
__device__ __forceinline__ void cpa_wait0()
{
    asm volatile("cp.async.wait_group 0;\n" ::: "memory");
}

// ---------------------------------------------------------------------------
// W convert: fp32 Wq|Wk|Wv -> bf16 hi/lo planes [d][192], col = mat*64+u
// ---------------------------------------------------------------------------
__global__ __launch_bounds__(256) void wconv_kernel(
    const float* __restrict__ Wq, const float* __restrict__ Wk,
    const float* __restrict__ Wv)
{
    const int idx = blockIdx.x * 256 + threadIdx.x;   // 0 .. 256*192-1
    const int d = idx / 192;
    const int n = idx % 192;
    const int mat = n >> 6;
    const int u   = n & 63;
    const float* W = (mat == 0) ? Wq : (mat == 1) ? Wk : Wv;
    const float v = W[d * UU + u];
    const __nv_bfloat16 h = __float2bfloat16(v);
    g_wh[idx] = h;
    g_wl[idx] = __float2bfloat16(v - __bfloat162float(h));
}

// ---------------------------------------------------------------------------
// Projection GEMM on tensor cores: [64 rows/block] x W[256,192], 3-term bf16.
// 8 warps: wr = w>>1 row group (16 rows), wc = w&1 col half (96 cols, 12 j).
// ---------------------------------------------------------------------------
__global__ __launch_bounds__(256) void proj_kernel(
    const float* __restrict__ x,
    const float* __restrict__ bq, const float* __restrict__ bk,
    const float* __restrict__ bv)
{
    __shared__ __align__(16) __nv_bfloat16 WH[64 * 192];   // 24 KB
    __shared__ __align__(16) __nv_bfloat16 WL[64 * 192];   // 24 KB

    const int R0  = blockIdx.x * 64;
    const int tid = threadIdx.x;
    const int w = tid >> 5, lane = tid & 31;
    const int wr = w >> 1, wc = w & 1;
    const int g = lane >> 2, q = lane & 3, lr = lane & 15;
    const int r0 = 16 * wr + g;

    float Of[12][4];
#pragma unroll
    for (int j = 0; j < 12; j++)
#pragma unroll
        for (int i = 0; i < 4; i++) Of[j][i] = 0.f;

    for (int kc = 0; kc < 4; kc++) {
        __syncthreads();
#pragma unroll
        for (int i0 = 0; i0 < 6; i0++) {
            const int i = tid + i0 * 256;
            const int d = i / 24;
            const int c = i % 24;
            const int sw = d * 192 + ((c ^ (d & 7)) * 8);
            *(uint4*)&WH[sw] = *(const uint4*)(g_wh + (size_t)(kc * 64 + d) * 192 + c * 8);
            *(uint4*)&WL[sw] = *(const uint4*)(g_wl + (size_t)(kc * 64 + d) * 192 + c * 8);
        }
        __syncthreads();

#pragma unroll
        for (int t = 0; t < 4; t++) {
            const int k0 = kc * 64 + 16 * t;
            float2 x0 = *(const float2*)(x + (size_t)(R0 + r0)     * DD + k0 + 2 * q);
            float2 x1 = *(const float2*)(x + (size_t)(R0 + r0 + 8) * DD + k0 + 2 * q);
            float2 x2 = *(const float2*)(x + (size_t)(R0 + r0)     * DD + k0 + 8 + 2 * q);
            float2 x3 = *(const float2*)(x + (size_t)(R0 + r0 + 8) * DD + k0 + 8 + 2 * q);
            uint32_t al0, al1, al2, al3;
            const uint32_t ah0 = bsplit(x0.x, x0.y, al0);
            const uint32_t ah1 = bsplit(x1.x, x1.y, al1);
            const uint32_t ah2 = bsplit(x2.x, x2.y, al2);
            const uint32_t ah3 = bsplit(x3.x, x3.y, al3);

#pragma unroll
            for (int j = 0; j < 12; j++) {
                const int cc = 12 * wc + j;
                const int r  = 16 * t + lr;
                const int sw = r * 192 + ((cc ^ (r & 7)) * 8);
                uint32_t wh0, wh1, wl0, wl1;
                ldsm2t(wh0, wh1, (uint32_t)__cvta_generic_to_shared(&WH[sw]));
                ldsm2t(wl0, wl1, (uint32_t)__cvta_generic_to_shared(&WL[sw]));
                mma16(Of[j], ah0, ah1, ah2, ah3, wh0, wh1);
                mma16(Of[j], ah0, ah1, ah2, ah3, wl0, wl1);
                mma16(Of[j], al0, al1, al2, al3, wh0, wh1);
            }
        }
    }

    // epilogue: bias, route by matrix, split K/V to bf16 hi/lo
#pragma unroll
    for (int j = 0; j < 12; j++) {
        const int n   = 96 * wc + 8 * j + 2 * q;
        const int mat = n >> 6;
        const int u   = n & 63;
        const float* bp = (mat == 0) ? bq : (mat == 1) ? bk : bv;
        const float b0v = bp[u], b1v = bp[u + 1];
        const float v00 = Of[j][0] + b0v, v01 = Of[j][1] + b1v;   // row r0
        const float v10 = Of[j][2] + b0v, v11 = Of[j][3] + b1v;   // row r0+8
        const size_t o0 = (size_t)(R0 + r0)     * UU + u;
        const size_t o1 = (size_t)(R0 + r0 + 8) * UU + u;
        if (mat == 0) {
            *(float2*)(g_q + o0) = make_float2(v00, v01);
            *(float2*)(g_q + o1) = make_float2(v10, v11);
        } else if (mat == 1) {
            uint32_t lo0, lo1;
            const uint32_t h0 = bsplit(v00, v01, lo0);
            const uint32_t h1 = bsplit(v10, v11, lo1);
            *(uint32_t*)(g_kh + o0) = h0;  *(uint32_t*)(g_kl + o0) = lo0;
            *(uint32_t*)(g_kh + o1) = h1;  *(uint32_t*)(g_kl + o1) = lo1;
        } else {
            uint32_t lo0, lo1;
            const uint32_t h0 = bsplit(v00, v01, lo0);
            const uint32_t h1 = bsplit(v10, v11, lo1);
            *(uint32_t*)(g_vh + o0) = h0;  *(uint32_t*)(g_vl + o0) = lo0;
            *(uint32_t*)(g_vh + o1) = h1;  *(uint32_t*)(g_vl + o1) = lo1;
        }
    }
}

// ---------------------------------------------------------------------------
// Flash attention: 128 threads = 4 warps; warp w owns rows [16w,16w+16) x all
// 64 keys (round-4 structure, 3 CTAs/SM). cp.async double-buffered K/V tiles,
// natural [key][u] layout, XOR-swizzled. S B-fragments via non-trans ldmatrix
// (pairs along u); PV B-fragments via trans ldmatrix (pairs along key).
// P = register remap. Online softmax state in registers.
// ---------------------------------------------------------------------------
__global__ __launch_bounds__(128, 3) void attn_kernel(float* __restrict__ out)
{
    extern __shared__ __align__(16) __nv_bfloat16 SB[];   // 2 bufs * 4 planes * 4096
    // plane base: SB + (buf*4 + arr)*4096 ; arr: 0=KH 1=KL 2=VH 3=VL

    const int b    = blockIdx.x >> 6;    // 64 blocks per batch
    const int mt   = blockIdx.x & 63;
    const int tid  = threadIdx.x;
    const int w    = tid >> 5;
    const int lane = tid & 31;
    const int g    = lane >> 2;
    const int q    = lane & 3;
    const int lr   = lane & 15;
    const int r0   = w * 16 + g;

    const __nv_bfloat16* khg = g_kh + (size_t)b * SS * UU;
    const __nv_bfloat16* klg = g_kl + (size_t)b * SS * UU;
    const __nv_bfloat16* vhg = g_vh + (size_t)b * SS * UU;
    const __nv_bfloat16* vlg = g_vl + (size_t)b * SS * UU;

    // ---- Q fragments: fold 1/8, split hi/lo ----
    uint32_t qh[4][4], ql[4][4];
    {
        const float* qg = g_q + ((size_t)b * SS + mt * 64) * UU;
#pragma unroll
        for (int t = 0; t < 4; t++) {
            float2 x0 = *(const float2*)(qg + (size_t)(r0)     * UU + 16 * t + 2 * q);
            float2 x1 = *(const float2*)(qg + (size_t)(r0 + 8) * UU + 16 * t + 2 * q);
            float2 x2 = *(const float2*)(qg + (size_t)(r0)     * UU + 16 * t + 8 + 2 * q);
            float2 x3 = *(const float2*)(qg + (size_t)(r0 + 8) * UU + 16 * t + 8 + 2 * q);
            qh[t][0] = bsplit(x0.x * 0.125f, x0.y * 0.125f, ql[t][0]);
            qh[t][1] = bsplit(x1.x * 0.125f, x1.y * 0.125f, ql[t][1]);
            qh[t][2] = bsplit(x2.x * 0.125f, x2.y * 0.125f, ql[t][2]);
            qh[t][3] = bsplit(x3.x * 0.125f, x3.y * 0.125f, ql[t][3]);
        }
    }

    float Of[8][4];
#pragma unroll
    for (int j = 0; j < 8; j++)
#pragma unroll
        for (int i = 0; i < 4; i++) Of[j][i] = 0.f;
    float m0 = -1e30f, m1 = -1e30f, l0 = 0.f, l1 = 0.f;

    auto load_tile = [&](int nt, int buf) {
        const size_t base = (size_t)(nt * 64) * UU;
        __nv_bfloat16* B0 = SB + (buf * 4 + 0) * 4096;
        __nv_bfloat16* B1 = SB + (buf * 4 + 1) * 4096;
        __nv_bfloat16* B2 = SB + (buf * 4 + 2) * 4096;
        __nv_bfloat16* B3 = SB + (buf * 4 + 3) * 4096;
        // 512 uint4 chunks per plane; 128 threads -> 4 chunks/thread/plane
#pragma unroll
        for (int i0 = 0; i0 < 4; i0++) {
            const int i   = tid + i0 * 128;
            const int row = i >> 3;
            const int c   = i & 7;
            const int sw  = row * 64 + ((c ^ (row & 7)) * 8);
            const size_t src = base + (size_t)row * UU + c * 8;
            cpa16(B0 + sw, khg + src);
            cpa16(B1 + sw, klg + src);
            cpa16(B2 + sw, vhg + src);
            cpa16(B3 + sw, vlg + src);
        }
        cpa_commit();
    };

    load_tile(0, 0);

    for (int nt = 0; nt < NTILES; nt++) {
        const int buf = nt & 1;
        cpa_wait0();       // this thread's copies of tile nt done
        __syncthreads();   // all threads' copies visible; prev compute done
        if (nt + 1 < NTILES) load_tile(nt + 1, buf ^ 1);

        const __nv_bfloat16* KHp = SB + (buf * 4 + 0) * 4096;
        const __nv_bfloat16* KLp = SB + (buf * 4 + 1) * 4096;
        const __nv_bfloat16* VHp = SB + (buf * 4 + 2) * 4096;
        const __nv_bfloat16* VLp = SB + (buf * 4 + 3) * 4096;

        // ---- S = Q K^T over all 64 keys ----
        float Sf[8][4];
#pragma unroll
        for (int j = 0; j < 8; j++) {
            Sf[j][0] = Sf[j][1] = Sf[j][2] = Sf[j][3] = 0.f;
            const int rowb = 8 * j + (lr & 7);
#pragma unroll
            for (int t = 0; t < 4; t++) {
                const int c  = 2 * t + (lr >> 3);
                const int sw = rowb * 64 + ((c ^ (rowb & 7)) * 8);
                uint32_t bh0, bh1, bl0, bl1;
                ldsm2n(bh0, bh1, (uint32_t)__cvta_generic_to_shared(&KHp[sw]));
                ldsm2n(bl0, bl1, (uint32_t)__cvta_generic_to_shared(&KLp[sw]));
                mma16(Sf[j], qh[t][0], qh[t][1], qh[t][2], qh[t][3], bh0, bh1);
                mma16(Sf[j], qh[t][0], qh[t][1], qh[t][2], qh[t][3], bl0, bl1);
                mma16(Sf[j], ql[t][0], ql[t][1], ql[t][2], ql[t][3], bh0, bh1);
            }
        }

        // ---- online softmax: row r0 <-> (c0,c1), row r0+8 <-> (c2,c3) ----
        float rm0 = -1e30f, rm1 = -1e30f;
#pragma unroll
        for (int j = 0; j < 8; j++) {
            rm0 = fmaxf(rm0, fmaxf(Sf[j][0], Sf[j][1]));
            rm1 = fmaxf(rm1, fmaxf(Sf[j][2], Sf[j][3]));
        }
        rm0 = fmaxf(rm0, __shfl_xor_sync(0xffffffffu, rm0, 1));
        rm0 = fmaxf(rm0, __shfl_xor_sync(0xffffffffu, rm0, 2));
        rm1 = fmaxf(rm1, __shfl_xor_sync(0xffffffffu, rm1, 1));
        rm1 = fmaxf(rm1, __shfl_xor_sync(0xffffffffu, rm1, 2));

        const float mn0 = fmaxf(m0, rm0);
        const float mn1 = fmaxf(m1, rm1);
        const float c0  = __expf(m0 - mn0);
        const float c1  = __expf(m1 - mn1);
        m0 = mn0; m1 = mn1;

        float rs0 = 0.f, rs1 = 0.f;
#pragma unroll
        for (int j = 0; j < 8; j++) {
            Sf[j][0] = __expf(Sf[j][0] - mn0); rs0 += Sf[j][0];
            Sf[j][1] = __expf(Sf[j][1] - mn0); rs0 += Sf[j][1];
            Sf[j][2] = __expf(Sf[j][2] - mn1); rs1 += Sf[j][2];
            Sf[j][3] = __expf(Sf[j][3] - mn1); rs1 += Sf[j][3];
        }
        rs0 += __shfl_xor_sync(0xffffffffu, rs0, 1);
        rs0 += __shfl_xor_sync(0xffffffffu, rs0, 2);
        rs1 += __shfl_xor_sync(0xffffffffu, rs1, 1);
        rs1 += __shfl_xor_sync(0xffffffffu, rs1, 2);

        l0 = l0 * c0 + rs0;
        l1 = l1 * c1 + rs1;
#pragma unroll
        for (int j = 0; j < 8; j++) {
            Of[j][0] *= c0; Of[j][1] *= c0;
            Of[j][2] *= c1; Of[j][3] *= c1;
        }

        // ---- P: C-fragment -> A-fragment remap in registers ----
        uint32_t ph01[8], ph23[8], pl01[8], pl23[8];
#pragma unroll
        for (int j = 0; j < 8; j++) {
            ph01[j] = bsplit(Sf[j][0], Sf[j][1], pl01[j]);
            ph23[j] = bsplit(Sf[j][2], Sf[j][3], pl23[j]);
        }

        // ---- O += P V over all 64 keys ----
#pragma unroll
        for (int j = 0; j < 8; j++) {      // u chunks
#pragma unroll
            for (int t = 0; t < 4; t++) {  // key 16-chunks
                const int r  = 16 * t + lr;
                const int sw = r * 64 + ((j ^ (r & 7)) * 8);
                uint32_t vh0, vh1, vl0, vl1;
                ldsm2t(vh0, vh1, (uint32_t)__cvta_generic_to_shared(&VHp[sw]));
                ldsm2t(vl0, vl1, (uint32_t)__cvta_generic_to_shared(&VLp[sw]));
                mma16(Of[j], ph01[2*t], ph23[2*t], ph01[2*t+1], ph23[2*t+1], vh0, vh1);
                mma16(Of[j], ph01[2*t], ph23[2*t], ph01[2*t+1], ph23[2*t+1], vl0, vl1);
                mma16(Of[j], pl01[2*t], pl23[2*t], pl01[2*t+1], pl23[2*t+1], vh0, vh1);
            }
        }
    }

    // ---- epilogue: normalize and store ----
    float* op = out + ((size_t)b * SS + mt * 64) * UU;
    const float inv0 = 1.f / l0;
    const float inv1 = 1.f / l1;
#pragma unroll
    for (int j = 0; j < 8; j++) {
        *(float2*)(op + (size_t)(r0)     * UU + 8 * j + 2 * q) =
            make_float2(Of[j][0] * inv0, Of[j][1] * inv0);
        *(float2*)(op + (size_t)(r0 + 8) * UU + 8 * j + 2 * q) =
            make_float2(Of[j][2] * inv1, Of[j][3] * inv1);
    }
}

// ---------------------------------------------------------------------------
extern "C" void kernel_launch(void* const* d_in, const int* in_sizes, int n_in,
                              void* d_out, int out_size)
{
    const float* x  = (const float*)d_in[0];
    const float* Wq = (const float*)d_in[1];
    const float* bq = (const float*)d_in[2];
    const float* Wk = (const float*)d_in[3];
    const float* bk = (const float*)d_in[4];
    const float* Wv = (const float*)d_in[5];
    const float* bv = (const float*)d_in[6];
    float* out = (float*)d_out;

    wconv_kernel<<<(DD * 192) / 256, 256>>>(Wq, Wk, Wv);
    proj_kernel<<<NROWS / 64, 256>>>(x, bq, bk, bv);

    const int smem_bytes = 2 * 4 * 4096 * (int)sizeof(__nv_bfloat16);   // 64 KB
    cudaFuncSetAttribute(attn_kernel, cudaFuncAttributeMaxDynamicSharedMemorySize,
                         smem_bytes);
    attn_kernel<<<BB * (SS / 64), 128, smem_bytes>>>(out);
}

// round 8
// speedup vs baseline: 1.9996x; 1.2832x over previous
#include <cuda_runtime.h>
#include <cuda_fp16.h>
#include <math.h>
#include <stdint.h>

#define BB 4
#define SS 4096
#define DD 256
#define UU 64
#define NTILES (SS / 64)
#define NROWS (BB * SS)        // 16384

// Scratch (no cudaMalloc allowed)
__device__ float   g_q [NROWS * UU];        // fp32  [b][s][u]
__device__ __half  g_k [NROWS * UU];        // K fp16 single plane, natural
__device__ __half  g_vh[NROWS * UU];        // V hi, natural
__device__ __half  g_vl[NROWS * UU];        // V lo
__device__ __half  g_wh[DD * 192];          // W combined [d][mat*64+u] hi
__device__ __half  g_wl[DD * 192];          // lo

// ---------------------------------------------------------------------------
// helpers
// ---------------------------------------------------------------------------
__device__ __forceinline__ void ldsm2t(uint32_t& r0, uint32_t& r1, uint32_t a)
{   // transposed: fragment pairs run across tile rows
    asm volatile("ldmatrix.sync.aligned.m8n8.x2.trans.shared.b16 {%0,%1},[%2];"
                 : "=r"(r0), "=r"(r1) : "r"(a));
}
__device__ __forceinline__ void ldsm2n(uint32_t& r0, uint32_t& r1, uint32_t a)
{   // non-transposed: fragment pairs run along tile row (contiguous)
    asm volatile("ldmatrix.sync.aligned.m8n8.x2.shared.b16 {%0,%1},[%2];"
                 : "=r"(r0), "=r"(r1) : "r"(a));
}
__device__ __forceinline__ void mma16(float d[4],
                                      uint32_t a0, uint32_t a1, uint32_t a2, uint32_t a3,
                                      uint32_t b0, uint32_t b1)
{
    asm volatile(
        "mma.sync.aligned.m16n8k16.row.col.f32.f16.f16.f32 "
        "{%0,%1,%2,%3},{%4,%5,%6,%7},{%8,%9},{%0,%1,%2,%3};\n"
        : "+f"(d[0]), "+f"(d[1]), "+f"(d[2]), "+f"(d[3])
        : "r"(a0), "r"(a1), "r"(a2), "r"(a3), "r"(b0), "r"(b1));
}
// split (x,y) into packed fp16x2 hi (returned) and lo (out-param)
__device__ __forceinline__ uint32_t hsplit(float x, float y, uint32_t& lo)
{
    __half2 h2 = __floats2half2_rn(x, y);
    const float rx = x - __half2float(__low2half(h2));
    const float ry = y - __half2float(__high2half(h2));
    __half2 l2 = __floats2half2_rn(rx, ry);
    lo = *(uint32_t*)&l2;
    return *(uint32_t*)&h2;
}
__device__ __forceinline__ uint32_t hpack(float x, float y)
{
    __half2 h2 = __floats2half2_rn(x, y);
    return *(uint32_t*)&h2;
}
__device__ __forceinline__ void cpa16(void* dst, const void* src)
{
    uint32_t d = (uint32_t)__cvta_generic_to_shared(dst);
    asm volatile("cp.async.cg.shared.global [%0],[%1],16;\n" :: "r"(d), "l"(src));
}
__device__ __forceinline__ void cpa_commit()
{
    asm volatile("cp.async.commit_group;\n" ::: "memory");
}
__device__ __forceinline__ void cpa_wait0()
{
    asm volatile("cp.async.wait_group 0;\n" ::: "memory");
}

// ---------------------------------------------------------------------------
// W convert: fp32 Wq|Wk|Wv -> fp16 hi/lo planes [d][192], col = mat*64+u
// ---------------------------------------------------------------------------
__global__ __launch_bounds__(256) void wconv_kernel(
    const float* __restrict__ Wq, const float* __restrict__ Wk,
    const float* __restrict__ Wv)
{
    const int idx = blockIdx.x * 256 + threadIdx.x;   // 0 .. 256*192-1
    const int d = idx / 192;
    const int n = idx % 192;
    const int mat = n >> 6;
    const int u   = n & 63;
    const float* W = (mat == 0) ? Wq : (mat == 1) ? Wk : Wv;
    const float v = W[d * UU + u];
    const __half h = __float2half_rn(v);
    g_wh[idx] = h;
    g_wl[idx] = __float2half_rn(v - __half2float(h));
}

// ---------------------------------------------------------------------------
// Projection GEMM on tensor cores: [64 rows/block] x W[256,192], fp16 3-term
// (error ~2^-22, negligible). 8 warps: wr row group, wc col half (96 cols).
// ---------------------------------------------------------------------------
__global__ __launch_bounds__(256) void proj_kernel(
    const float* __restrict__ x,
    const float* __restrict__ bq, const float* __restrict__ bk,
    const float* __restrict__ bv)
{
    __shared__ __align__(16) __half WH[64 * 192];   // 24 KB
    __shared__ __align__(16) __half WL[64 * 192];   // 24 KB

    const int R0  = blockIdx.x * 64;
    const int tid = threadIdx.x;
    const int w = tid >> 5, lane = tid & 31;
    const int wr = w >> 1, wc = w & 1;
    const int g = lane >> 2, q = lane & 3, lr = lane & 15;
    const int r0 = 16 * wr + g;

    float Of[12][4];
#pragma unroll
    for (int j = 0; j < 12; j++)
#pragma unroll
        for (int i = 0; i < 4; i++) Of[j][i] = 0.f;

    for (int kc = 0; kc < 4; kc++) {
        __syncthreads();
#pragma unroll
        for (int i0 = 0; i0 < 6; i0++) {
            const int i = tid + i0 * 256;
            const int d = i / 24;
            const int c = i % 24;
            const int sw = d * 192 + ((c ^ (d & 7)) * 8);
            *(uint4*)&WH[sw] = *(const uint4*)(g_wh + (size_t)(kc * 64 + d) * 192 + c * 8);
            *(uint4*)&WL[sw] = *(const uint4*)(g_wl + (size_t)(kc * 64 + d) * 192 + c * 8);
        }
        __syncthreads();

#pragma unroll
        for (int t = 0; t < 4; t++) {
            const int k0 = kc * 64 + 16 * t;
            float2 x0 = *(const float2*)(x + (size_t)(R0 + r0)     * DD + k0 + 2 * q);
            float2 x1 = *(const float2*)(x + (size_t)(R0 + r0 + 8) * DD + k0 + 2 * q);
            float2 x2 = *(const float2*)(x + (size_t)(R0 + r0)     * DD + k0 + 8 + 2 * q);
            float2 x3 = *(const float2*)(x + (size_t)(R0 + r0 + 8) * DD + k0 + 8 + 2 * q);
            uint32_t al0, al1, al2, al3;
            const uint32_t ah0 = hsplit(x0.x, x0.y, al0);
            const uint32_t ah1 = hsplit(x1.x, x1.y, al1);
            const uint32_t ah2 = hsplit(x2.x, x2.y, al2);
            const uint32_t ah3 = hsplit(x3.x, x3.y, al3);

#pragma unroll
            for (int j = 0; j < 12; j++) {
                const int cc = 12 * wc + j;
                const int r  = 16 * t + lr;
                const int sw = r * 192 + ((cc ^ (r & 7)) * 8);
                uint32_t wh0, wh1, wl0, wl1;
                ldsm2t(wh0, wh1, (uint32_t)__cvta_generic_to_shared(&WH[sw]));
                ldsm2t(wl0, wl1, (uint32_t)__cvta_generic_to_shared(&WL[sw]));
                mma16(Of[j], ah0, ah1, ah2, ah3, wh0, wh1);
                mma16(Of[j], ah0, ah1, ah2, ah3, wl0, wl1);
                mma16(Of[j], al0, al1, al2, al3, wh0, wh1);
            }
        }
    }

    // epilogue: bias, route by matrix; K -> fp16 single, V -> fp16 hi/lo
#pragma unroll
    for (int j = 0; j < 12; j++) {
        const int n   = 96 * wc + 8 * j + 2 * q;
        const int mat = n >> 6;
        const int u   = n & 63;
        const float* bp = (mat == 0) ? bq : (mat == 1) ? bk : bv;
        const float b0v = bp[u], b1v = bp[u + 1];
        const float v00 = Of[j][0] + b0v, v01 = Of[j][1] + b1v;   // row r0
        const float v10 = Of[j][2] + b0v, v11 = Of[j][3] + b1v;   // row r0+8
        const size_t o0 = (size_t)(R0 + r0)     * UU + u;
        const size_t o1 = (size_t)(R0 + r0 + 8) * UU + u;
        if (mat == 0) {
            *(float2*)(g_q + o0) = make_float2(v00, v01);
            *(float2*)(g_q + o1) = make_float2(v10, v11);
        } else if (mat == 1) {
            *(uint32_t*)(g_k + o0) = hpack(v00, v01);
            *(uint32_t*)(g_k + o1) = hpack(v10, v11);
        } else {
            uint32_t lo0, lo1;
            const uint32_t h0 = hsplit(v00, v01, lo0);
            const uint32_t h1 = hsplit(v10, v11, lo1);
            *(uint32_t*)(g_vh + o0) = h0;  *(uint32_t*)(g_vl + o0) = lo0;
            *(uint32_t*)(g_vh + o1) = h1;  *(uint32_t*)(g_vl + o1) = lo1;
        }
    }
}

// ---------------------------------------------------------------------------
// Flash attention, fp16 2-term: S = (q_hi+q_lo)·K ;  O = p·(V_hi+V_lo).
// 128 threads = 4 warps; warp w owns rows [16w,16w+16) x all 64 keys.
// cp.async double-buffered tiles: 3 planes (K, VH, VL), XOR-swizzled.
// ---------------------------------------------------------------------------
__global__ __launch_bounds__(128, 3) void attn_kernel(float* __restrict__ out)
{
    extern __shared__ __align__(16) __half SB[];   // 2 bufs * 3 planes * 4096
    // plane base: SB + (buf*3 + arr)*4096 ; arr: 0=K 1=VH 2=VL

    const int b    = blockIdx.x >> 6;    // 64 blocks per batch
    const int mt   = blockIdx.x & 63;
    const int tid  = threadIdx.x;
    const int w    = tid >> 5;
    const int lane = tid & 31;
    const int g    = lane >> 2;
    const int q    = lane & 3;
    const int lr   = lane & 15;
    const int r0   = w * 16 + g;

    const __half* kg  = g_k  + (size_t)b * SS * UU;
    const __half* vhg = g_vh + (size_t)b * SS * UU;
    const __half* vlg = g_vl + (size_t)b * SS * UU;

    // ---- Q fragments: fold 1/8, split hi/lo ----
    uint32_t qh[4][4], ql[4][4];
    {
        const float* qg = g_q + ((size_t)b * SS + mt * 64) * UU;
#pragma unroll
        for (int t = 0; t < 4; t++) {
            float2 x0 = *(const float2*)(qg + (size_t)(r0)     * UU + 16 * t + 2 * q);
            float2 x1 = *(const float2*)(qg + (size_t)(r0 + 8) * UU + 16 * t + 2 * q);
            float2 x2 = *(const float2*)(qg + (size_t)(r0)     * UU + 16 * t + 8 + 2 * q);
            float2 x3 = *(const float2*)(qg + (size_t)(r0 + 8) * UU + 16 * t + 8 + 2 * q);
            qh[t][0] = hsplit(x0.x * 0.125f, x0.y * 0.125f, ql[t][0]);
            qh[t][1] = hsplit(x1.x * 0.125f, x1.y * 0.125f, ql[t][1]);
            qh[t][2] = hsplit(x2.x * 0.125f, x2.y * 0.125f, ql[t][2]);
            qh[t][3] = hsplit(x3.x * 0.125f, x3.y * 0.125f, ql[t][3]);
        }
    }

    float Of[8][4];
#pragma unroll
    for (int j = 0; j < 8; j++)
#pragma unroll
        for (int i = 0; i < 4; i++) Of[j][i] = 0.f;
    float m0 = -1e30f, m1 = -1e30f, l0 = 0.f, l1 = 0.f;

    auto load_tile = [&](int nt, int buf) {
        const size_t base = (size_t)(nt * 64) * UU;
        __half* B0 = SB + (buf * 3 + 0) * 4096;
        __half* B1 = SB + (buf * 3 + 1) * 4096;
        __half* B2 = SB + (buf * 3 + 2) * 4096;
        // 512 uint4 chunks per plane; 128 threads -> 4 chunks/thread/plane
#pragma unroll
        for (int i0 = 0; i0 < 4; i0++) {
            const int i   = tid + i0 * 128;
            const int row = i >> 3;
            const int c   = i & 7;
            const int sw  = row * 64 + ((c ^ (row & 7)) * 8);
            const size_t src = base + (size_t)row * UU + c * 8;
            cpa16(B0 + sw, kg  + src);
            cpa16(B1 + sw, vhg + src);
            cpa16(B2 + sw, vlg + src);
        }
        cpa_commit();
    };

    load_tile(0, 0);

    for (int nt = 0; nt < NTILES; nt++) {
        const int buf = nt & 1;
        cpa_wait0();       // this thread's copies of tile nt done
        __syncthreads();   // all threads' copies visible; prev compute done
        if (nt + 1 < NTILES) load_tile(nt + 1, buf ^ 1);

        const __half* Kp  = SB + (buf * 3 + 0) * 4096;
        const __half* VHp = SB + (buf * 3 + 1) * 4096;
        const __half* VLp = SB + (buf * 3 + 2) * 4096;

        // ---- S = (q_hi + q_lo) K^T over all 64 keys ----
        float Sf[8][4];
#pragma unroll
        for (int j = 0; j < 8; j++) {
            Sf[j][0] = Sf[j][1] = Sf[j][2] = Sf[j][3] = 0.f;
            const int rowb = 8 * j + (lr & 7);
#pragma unroll
            for (int t = 0; t < 4; t++) {
                const int c  = 2 * t + (lr >> 3);
                const int sw = rowb * 64 + ((c ^ (rowb & 7)) * 8);
                uint32_t b0, b1;
                ldsm2n(b0, b1, (uint32_t)__cvta_generic_to_shared(&Kp[sw]));
                mma16(Sf[j], qh[t][0], qh[t][1], qh[t][2], qh[t][3], b0, b1);
                mma16(Sf[j], ql[t][0], ql[t][1], ql[t][2], ql[t][3], b0, b1);
            }
        }

        // ---- online softmax: row r0 <-> (c0,c1), row r0+8 <-> (c2,c3) ----
        float rm0 = -1e30f, rm1 = -1e30f;
#pragma unroll
        for (int j = 0; j < 8; j++) {
            rm0 = fmaxf(rm0, fmaxf(Sf[j][0], Sf[j][1]));
            rm1 = fmaxf(rm1, fmaxf(Sf[j][2], Sf[j][3]));
        }
        rm0 = fmaxf(rm0, __shfl_xor_sync(0xffffffffu, rm0, 1));
        rm0 = fmaxf(rm0, __shfl_xor_sync(0xffffffffu, rm0, 2));
        rm1 = fmaxf(rm1, __shfl_xor_sync(0xffffffffu, rm1, 1));
        rm1 = fmaxf(rm1, __shfl_xor_sync(0xffffffffu, rm1, 2));

        const float mn0 = fmaxf(m0, rm0);
        const float mn1 = fmaxf(m1, rm1);
        const float c0  = __expf(m0 - mn0);
        const float c1  = __expf(m1 - mn1);
        m0 = mn0; m1 = mn1;

        float rs0 = 0.f, rs1 = 0.f;
#pragma unroll
        for (int j = 0; j < 8; j++) {
            Sf[j][0] = __expf(Sf[j][0] - mn0); rs0 += Sf[j][0];
            Sf[j][1] = __expf(Sf[j][1] - mn0); rs0 += Sf[j][1];
            Sf[j][2] = __expf(Sf[j][2] - mn1); rs1 += Sf[j][2];
            Sf[j][3] = __expf(Sf[j][3] - mn1); rs1 += Sf[j][3];
        }
        rs0 += __shfl_xor_sync(0xffffffffu, rs0, 1);
        rs0 += __shfl_xor_sync(0xffffffffu, rs0, 2);
        rs1 += __shfl_xor_sync(0xffffffffu, rs1, 1);
        rs1 += __shfl_xor_sync(0xffffffffu, rs1, 2);

        l0 = l0 * c0 + rs0;
        l1 = l1 * c1 + rs1;
#pragma unroll
        for (int j = 0; j < 8; j++) {
            Of[j][0] *= c0; Of[j][1] *= c0;
            Of[j][2] *= c1; Of[j][3] *= c1;
        }

        // ---- P: C-fragment -> A-fragment remap (fp16, no split) ----
        uint32_t p01[8], p23[8];
#pragma unroll
        for (int j = 0; j < 8; j++) {
            p01[j] = hpack(Sf[j][0], Sf[j][1]);
            p23[j] = hpack(Sf[j][2], Sf[j][3]);
        }

        // ---- O += P (V_hi + V_lo) over all 64 keys ----
#pragma unroll
        for (int j = 0; j < 8; j++) {      // u chunks
#pragma unroll
            for (int t = 0; t < 4; t++) {  // key 16-chunks
                const int r  = 16 * t + lr;
                const int sw = r * 64 + ((j ^ (r & 7)) * 8);
                uint32_t vh0, vh1, vl0, vl1;
                ldsm2t(vh0, vh1, (uint32_t)__cvta_generic_to_shared(&VHp[sw]));
                ldsm2t(vl0, vl1, (uint32_t)__cvta_generic_to_shared(&VLp[sw]));
                mma16(Of[j], p01[2*t], p23[2*t], p01[2*t+1], p23[2*t+1], vh0, vh1);
                mma16(Of[j], p01[2*t], p23[2*t], p01[2*t+1], p23[2*t+1], vl0, vl1);
            }
        }
    }

    // ---- epilogue: normalize and store ----
    float* op = out + ((size_t)b * SS + mt * 64) * UU;
    const float inv0 = 1.f / l0;
    const float inv1 = 1.f / l1;
#pragma unroll
    for (int j = 0; j < 8; j++) {
        *(float2*)(op + (size_t)(r0)     * UU + 8 * j + 2 * q) =
            make_float2(Of[j][0] * inv0, Of[j][1] * inv0);
        *(float2*)(op + (size_t)(r0 + 8) * UU + 8 * j + 2 * q) =
            make_float2(Of[j][2] * inv1, Of[j][3] * inv1);
    }
}

// ---------------------------------------------------------------------------
extern "C" void kernel_launch(void* const* d_in, const int* in_sizes, int n_in,
                              void* d_out, int out_size)
{
    const float* x  = (const float*)d_in[0];
    const float* Wq = (const float*)d_in[1];
    const float* bq = (const float*)d_in[2];
    const float* Wk = (const float*)d_in[3];
    const float* bk = (const float*)d_in[4];
    const float* Wv = (const float*)d_in[5];
    const float* bv = (const float*)d_in[6];
    float* out = (float*)d_out;

    wconv_kernel<<<(DD * 192) / 256, 256>>>(Wq, Wk, Wv);
    proj_kernel<<<NROWS / 64, 256>>>(x, bq, bk, bv);

    const int smem_bytes = 2 * 3 * 4096 * (int)sizeof(__half);   // 48 KB
    cudaFuncSetAttribute(attn_kernel, cudaFuncAttributeMaxDynamicSharedMemorySize,
                         smem_bytes);
    attn_kernel<<<BB * (SS / 64), 128, smem_bytes>>>(out);
}

// round 9
// speedup vs baseline: 2.8739x; 1.4373x over previous
#include <cuda_runtime.h>
#include <cuda_fp16.h>
#include <math.h>
#include <stdint.h>

#define BB 4
#define SS 4096
#define DD 256
#define UU 64
#define NTILES (SS / 64)
#define NROWS (BB * SS)        // 16384

// Scratch (no cudaMalloc allowed)
__device__ __half  g_q [NROWS * UU];        // Q fp16, pre-scaled by 1/8, natural
__device__ __half  g_k [NROWS * UU];        // K fp16, natural
__device__ __half  g_v [NROWS * UU];        // V fp16, natural
__device__ __half  g_wh[DD * 192];          // W combined [d][mat*64+u] hi (Wq pre-scaled)
__device__ __half  g_wl[DD * 192];          // lo

// ---------------------------------------------------------------------------
// helpers
// ---------------------------------------------------------------------------
__device__ __forceinline__ void ldsm4t(uint32_t& r0, uint32_t& r1,
                                       uint32_t& r2, uint32_t& r3, uint32_t a)
{
    asm volatile("ldmatrix.sync.aligned.m8n8.x4.trans.shared.b16 {%0,%1,%2,%3},[%4];"
                 : "=r"(r0), "=r"(r1), "=r"(r2), "=r"(r3) : "r"(a));
}
__device__ __forceinline__ void ldsm4n(uint32_t& r0, uint32_t& r1,
                                       uint32_t& r2, uint32_t& r3, uint32_t a)
{
    asm volatile("ldmatrix.sync.aligned.m8n8.x4.shared.b16 {%0,%1,%2,%3},[%4];"
                 : "=r"(r0), "=r"(r1), "=r"(r2), "=r"(r3) : "r"(a));
}
__device__ __forceinline__ void ldsm2t(uint32_t& r0, uint32_t& r1, uint32_t a)
{
    asm volatile("ldmatrix.sync.aligned.m8n8.x2.trans.shared.b16 {%0,%1},[%2];"
                 : "=r"(r0), "=r"(r1) : "r"(a));
}
__device__ __forceinline__ void mma16(float d[4],
                                      uint32_t a0, uint32_t a1, uint32_t a2, uint32_t a3,
                                      uint32_t b0, uint32_t b1)
{
    asm volatile(
        "mma.sync.aligned.m16n8k16.row.col.f32.f16.f16.f32 "
        "{%0,%1,%2,%3},{%4,%5,%6,%7},{%8,%9},{%0,%1,%2,%3};\n"
        : "+f"(d[0]), "+f"(d[1]), "+f"(d[2]), "+f"(d[3])
        : "r"(a0), "r"(a1), "r"(a2), "r"(a3), "r"(b0), "r"(b1));
}
__device__ __forceinline__ uint32_t hsplit(float x, float y, uint32_t& lo)
{
    __half2 h2 = __floats2half2_rn(x, y);
    const float rx = x - __half2float(__low2half(h2));
    const float ry = y - __half2float(__high2half(h2));
    __half2 l2 = __floats2half2_rn(rx, ry);
    lo = *(uint32_t*)&l2;
    return *(uint32_t*)&h2;
}
__device__ __forceinline__ uint32_t hpack(float x, float y)
{
    __half2 h2 = __floats2half2_rn(x, y);
    return *(uint32_t*)&h2;
}
__device__ __forceinline__ void cpa16(void* dst, const void* src)
{
    uint32_t d = (uint32_t)__cvta_generic_to_shared(dst);
    asm volatile("cp.async.cg.shared.global [%0],[%1],16;\n" :: "r"(d), "l"(src));
}
__device__ __forceinline__ void cpa_commit()
{
    asm volatile("cp.async.commit_group;\n" ::: "memory");
}
__device__ __forceinline__ void cpa_wait0()
{
    asm volatile("cp.async.wait_group 0;\n" ::: "memory");
}

// ---------------------------------------------------------------------------
// W convert: fp32 Wq|Wk|Wv -> fp16 hi/lo planes [d][192]; Wq pre-scaled by 1/8
// ---------------------------------------------------------------------------
__global__ __launch_bounds__(256) void wconv_kernel(
    const float* __restrict__ Wq, const float* __restrict__ Wk,
    const float* __restrict__ Wv)
{
    const int idx = blockIdx.x * 256 + threadIdx.x;   // 0 .. 256*192-1
    const int d = idx / 192;
    const int n = idx % 192;
    const int mat = n >> 6;
    const int u   = n & 63;
    const float* W = (mat == 0) ? Wq : (mat == 1) ? Wk : Wv;
    float v = W[d * UU + u];
    if (mat == 0) v *= 0.125f;                 // fold softmax scale into Wq
    const __half h = __float2half_rn(v);
    g_wh[idx] = h;
    g_wl[idx] = __float2half_rn(v - __half2float(h));
}

// ---------------------------------------------------------------------------
// Projection GEMM on tensor cores: [64 rows/block] x W[256,192], fp16 3-term.
// All outputs stored as single fp16 planes (Q pre-scaled).
// ---------------------------------------------------------------------------
__global__ __launch_bounds__(256) void proj_kernel(
    const float* __restrict__ x,
    const float* __restrict__ bq, const float* __restrict__ bk,
    const float* __restrict__ bv)
{
    __shared__ __align__(16) __half WH[64 * 192];   // 24 KB
    __shared__ __align__(16) __half WL[64 * 192];   // 24 KB

    const int R0  = blockIdx.x * 64;
    const int tid = threadIdx.x;
    const int w = tid >> 5, lane = tid & 31;
    const int wr = w >> 1, wc = w & 1;
    const int g = lane >> 2, q = lane & 3, lr = lane & 15;
    const int r0 = 16 * wr + g;

    float Of[12][4];
#pragma unroll
    for (int j = 0; j < 12; j++)
#pragma unroll
        for (int i = 0; i < 4; i++) Of[j][i] = 0.f;

    for (int kc = 0; kc < 4; kc++) {
        __syncthreads();
#pragma unroll
        for (int i0 = 0; i0 < 6; i0++) {
            const int i = tid + i0 * 256;
            const int d = i / 24;
            const int c = i % 24;
            const int sw = d * 192 + ((c ^ (d & 7)) * 8);
            *(uint4*)&WH[sw] = *(const uint4*)(g_wh + (size_t)(kc * 64 + d) * 192 + c * 8);
            *(uint4*)&WL[sw] = *(const uint4*)(g_wl + (size_t)(kc * 64 + d) * 192 + c * 8);
        }
        __syncthreads();

#pragma unroll
        for (int t = 0; t < 4; t++) {
            const int k0 = kc * 64 + 16 * t;
            float2 x0 = *(const float2*)(x + (size_t)(R0 + r0)     * DD + k0 + 2 * q);
            float2 x1 = *(const float2*)(x + (size_t)(R0 + r0 + 8) * DD + k0 + 2 * q);
            float2 x2 = *(const float2*)(x + (size_t)(R0 + r0)     * DD + k0 + 8 + 2 * q);
            float2 x3 = *(const float2*)(x + (size_t)(R0 + r0 + 8) * DD + k0 + 8 + 2 * q);
            uint32_t al0, al1, al2, al3;
            const uint32_t ah0 = hsplit(x0.x, x0.y, al0);
            const uint32_t ah1 = hsplit(x1.x, x1.y, al1);
            const uint32_t ah2 = hsplit(x2.x, x2.y, al2);
            const uint32_t ah3 = hsplit(x3.x, x3.y, al3);

#pragma unroll
            for (int j = 0; j < 12; j++) {
                const int cc = 12 * wc + j;
                const int r  = 16 * t + lr;
                const int sw = r * 192 + ((cc ^ (r & 7)) * 8);
                uint32_t wh0, wh1, wl0, wl1;
                ldsm2t(wh0, wh1, (uint32_t)__cvta_generic_to_shared(&WH[sw]));
                ldsm2t(wl0, wl1, (uint32_t)__cvta_generic_to_shared(&WL[sw]));
                mma16(Of[j], ah0, ah1, ah2, ah3, wh0, wh1);
                mma16(Of[j], ah0, ah1, ah2, ah3, wl0, wl1);
                mma16(Of[j], al0, al1, al2, al3, wh0, wh1);
            }
        }
    }

    // epilogue: bias, route by matrix, store single fp16 planes
#pragma unroll
    for (int j = 0; j < 12; j++) {
        const int n   = 96 * wc + 8 * j + 2 * q;
        const int mat = n >> 6;
        const int u   = n & 63;
        const float* bp = (mat == 0) ? bq : (mat == 1) ? bk : bv;
        const float bscale = (mat == 0) ? 0.125f : 1.f;   // Wq was pre-scaled
        const float b0v = bp[u] * bscale, b1v = bp[u + 1] * bscale;
        const float v00 = Of[j][0] + b0v, v01 = Of[j][1] + b1v;   // row r0
        const float v10 = Of[j][2] + b0v, v11 = Of[j][3] + b1v;   // row r0+8
        const size_t o0 = (size_t)(R0 + r0)     * UU + u;
        const size_t o1 = (size_t)(R0 + r0 + 8) * UU + u;
        __half* dst = (mat == 0) ? g_q : (mat == 1) ? g_k : g_v;
        *(uint32_t*)(dst + o0) = hpack(v00, v01);
        *(uint32_t*)(dst + o1) = hpack(v10, v11);
    }
}

// ---------------------------------------------------------------------------
// Flash attention, plain fp16 operands, fp32 accum + fp32 softmax.
// 128 threads = 4 warps; warp w owns rows [16w,16w+16) x all 64 keys.
// cp.async double-buffered tiles: 2 planes (K, V), XOR-swizzled.
// All B-fragments via ldmatrix.x4 (half the ldsm issue of .x2).
// ---------------------------------------------------------------------------
__global__ __launch_bounds__(128, 4) void attn_kernel(float* __restrict__ out)
{
    extern __shared__ __align__(16) __half SB[];   // 2 bufs * 2 planes * 4096
    // plane base: SB + (buf*2 + arr)*4096 ; arr: 0=K 1=V

    const int b    = blockIdx.x >> 6;    // 64 blocks per batch
    const int mt   = blockIdx.x & 63;
    const int tid  = threadIdx.x;
    const int w    = tid >> 5;
    const int lane = tid & 31;
    const int g    = lane >> 2;
    const int q    = lane & 3;
    const int r0   = w * 16 + g;

    const __half* kg = g_k + (size_t)b * SS * UU;
    const __half* vg = g_v + (size_t)b * SS * UU;

    // ---- Q fragments: direct fp16 loads (pre-scaled in proj) ----
    uint32_t qh[4][4];
    {
        const __half* qg = g_q + ((size_t)b * SS + mt * 64) * UU;
#pragma unroll
        for (int t = 0; t < 4; t++) {
            qh[t][0] = *(const uint32_t*)(qg + (size_t)(r0)     * UU + 16 * t + 2 * q);
            qh[t][1] = *(const uint32_t*)(qg + (size_t)(r0 + 8) * UU + 16 * t + 2 * q);
            qh[t][2] = *(const uint32_t*)(qg + (size_t)(r0)     * UU + 16 * t + 8 + 2 * q);
            qh[t][3] = *(const uint32_t*)(qg + (size_t)(r0 + 8) * UU + 16 * t + 8 + 2 * q);
        }
    }

    float Of[8][4];
#pragma unroll
    for (int j = 0; j < 8; j++)
#pragma unroll
        for (int i = 0; i < 4; i++) Of[j][i] = 0.f;
    float m0 = -1e30f, m1 = -1e30f, l0 = 0.f, l1 = 0.f;

    auto load_tile = [&](int nt, int buf) {
        const size_t base = (size_t)(nt * 64) * UU;
        __half* B0 = SB + (buf * 2 + 0) * 4096;
        __half* B1 = SB + (buf * 2 + 1) * 4096;
#pragma unroll
        for (int i0 = 0; i0 < 4; i0++) {
            const int i   = tid + i0 * 128;
            const int row = i >> 3;
            const int c   = i & 7;
            const int sw  = row * 64 + ((c ^ (row & 7)) * 8);
            const size_t src = base + (size_t)row * UU + c * 8;
            cpa16(B0 + sw, kg + src);
            cpa16(B1 + sw, vg + src);
        }
        cpa_commit();
    };

    load_tile(0, 0);

    for (int nt = 0; nt < NTILES; nt++) {
        const int buf = nt & 1;
        cpa_wait0();       // this thread's copies of tile nt done
        __syncthreads();   // all threads' copies visible; prev compute done
        if (nt + 1 < NTILES) load_tile(nt + 1, buf ^ 1);

        const __half* Kp = SB + (buf * 2 + 0) * 4096;
        const __half* Vp = SB + (buf * 2 + 1) * 4096;

        // ---- S = Q K^T over all 64 keys (x4 ldsm: 2 per j) ----
        float Sf[8][4];
#pragma unroll
        for (int j = 0; j < 8; j++) {
            Sf[j][0] = Sf[j][1] = Sf[j][2] = Sf[j][3] = 0.f;
            const int r = 8 * j + (lane & 7);
#pragma unroll
            for (int t0 = 0; t0 < 4; t0 += 2) {
                const int c  = 2 * t0 + (lane >> 3);         // matrices t0, t0+1
                const int sw = r * 64 + ((c ^ (r & 7)) * 8);
                uint32_t b0, b1, b2, b3;
                ldsm4n(b0, b1, b2, b3, (uint32_t)__cvta_generic_to_shared(&Kp[sw]));
                mma16(Sf[j], qh[t0][0],   qh[t0][1],   qh[t0][2],   qh[t0][3],   b0, b1);
                mma16(Sf[j], qh[t0+1][0], qh[t0+1][1], qh[t0+1][2], qh[t0+1][3], b2, b3);
            }
        }

        // ---- online softmax: row r0 <-> (c0,c1), row r0+8 <-> (c2,c3) ----
        float rm0 = -1e30f, rm1 = -1e30f;
#pragma unroll
        for (int j = 0; j < 8; j++) {
            rm0 = fmaxf(rm0, fmaxf(Sf[j][0], Sf[j][1]));
            rm1 = fmaxf(rm1, fmaxf(Sf[j][2], Sf[j][3]));
        }
        rm0 = fmaxf(rm0, __shfl_xor_sync(0xffffffffu, rm0, 1));
        rm0 = fmaxf(rm0, __shfl_xor_sync(0xffffffffu, rm0, 2));
        rm1 = fmaxf(rm1, __shfl_xor_sync(0xffffffffu, rm1, 1));
        rm1 = fmaxf(rm1, __shfl_xor_sync(0xffffffffu, rm1, 2));

        const float mn0 = fmaxf(m0, rm0);
        const float mn1 = fmaxf(m1, rm1);
        const float c0  = __expf(m0 - mn0);
        const float c1  = __expf(m1 - mn1);
        m0 = mn0; m1 = mn1;

        float rs0 = 0.f, rs1 = 0.f;
#pragma unroll
        for (int j = 0; j < 8; j++) {
            Sf[j][0] = __expf(Sf[j][0] - mn0); rs0 += Sf[j][0];
            Sf[j][1] = __expf(Sf[j][1] - mn0); rs0 += Sf[j][1];
            Sf[j][2] = __expf(Sf[j][2] - mn1); rs1 += Sf[j][2];
            Sf[j][3] = __expf(Sf[j][3] - mn1); rs1 += Sf[j][3];
        }
        rs0 += __shfl_xor_sync(0xffffffffu, rs0, 1);
        rs0 += __shfl_xor_sync(0xffffffffu, rs0, 2);
        rs1 += __shfl_xor_sync(0xffffffffu, rs1, 1);
        rs1 += __shfl_xor_sync(0xffffffffu, rs1, 2);

        l0 = l0 * c0 + rs0;
        l1 = l1 * c1 + rs1;
#pragma unroll
        for (int j = 0; j < 8; j++) {
            Of[j][0] *= c0; Of[j][1] *= c0;
            Of[j][2] *= c1; Of[j][3] *= c1;
        }

        // ---- P: C-fragment -> A-fragment remap (fp16) ----
        uint32_t p01[8], p23[8];
#pragma unroll
        for (int j = 0; j < 8; j++) {
            p01[j] = hpack(Sf[j][0], Sf[j][1]);
            p23[j] = hpack(Sf[j][2], Sf[j][3]);
        }

        // ---- O += P V (x4 trans ldsm serves j-pair at once) ----
#pragma unroll
        for (int jp = 0; jp < 4; jp++) {   // u chunk pairs (j=2jp, 2jp+1)
#pragma unroll
            for (int t = 0; t < 4; t++) {  // key 16-chunks
                const int r  = 16 * t + (lane & 15);
                const int c  = 2 * jp + (lane >> 4);         // cols 8j, 8(j+1)
                const int sw = r * 64 + ((c ^ (r & 7)) * 8);
                uint32_t v0, v1, v2, v3;
                ldsm4t(v0, v1, v2, v3, (uint32_t)__cvta_generic_to_shared(&Vp[sw]));
                mma16(Of[2*jp],   p01[2*t], p23[2*t], p01[2*t+1], p23[2*t+1], v0, v1);
                mma16(Of[2*jp+1], p01[2*t], p23[2*t], p01[2*t+1], p23[2*t+1], v2, v3);
            }
        }
    }

    // ---- epilogue: normalize and store ----
    float* op = out + ((size_t)b * SS + mt * 64) * UU;
    const float inv0 = 1.f / l0;
    const float inv1 = 1.f / l1;
#pragma unroll
    for (int j = 0; j < 8; j++) {
        *(float2*)(op + (size_t)(r0)     * UU + 8 * j + 2 * q) =
            make_float2(Of[j][0] * inv0, Of[j][1] * inv0);
        *(float2*)(op + (size_t)(r0 + 8) * UU + 8 * j + 2 * q) =
            make_float2(Of[j][2] * inv1, Of[j][3] * inv1);
    }
}

// ---------------------------------------------------------------------------
extern "C" void kernel_launch(void* const* d_in, const int* in_sizes, int n_in,
                              void* d_out, int out_size)
{
    const float* x  = (const float*)d_in[0];
    const float* Wq = (const float*)d_in[1];
    const float* bq = (const float*)d_in[2];
    const float* Wk = (const float*)d_in[3];
    const float* bk = (const float*)d_in[4];
    const float* Wv = (const float*)d_in[5];
    const float* bv = (const float*)d_in[6];
    float* out = (float*)d_out;

    wconv_kernel<<<(DD * 192) / 256, 256>>>(Wq, Wk, Wv);
    proj_kernel<<<NROWS / 64, 256>>>(x, bq, bk, bv);

    const int smem_bytes = 2 * 2 * 4096 * (int)sizeof(__half);   // 32 KB
    cudaFuncSetAttribute(attn_kernel, cudaFuncAttributeMaxDynamicSharedMemorySize,
                         smem_bytes);
    attn_kernel<<<BB * (SS / 64), 128, smem_bytes>>>(out);
}